// round 2
// baseline (speedup 1.0000x reference)
#include <cuda_runtime.h>
#include <math.h>

#define S_DIM 1024
#define T_DIM 1024
#define HID_DIM 128
#define NE_MAX 32000
#define KSPLIT 2

// Scratch (allocation-free rule: __device__ globals). 16B-aligned for float4.
__device__ __align__(16) float g_resp[(size_t)NE_MAX * S_DIM];         // [ne][S]
__device__ __align__(16) float g_part[(size_t)KSPLIT * S_DIM * T_DIM]; // partials

// ---------------------------------------------------------------------------
// Kernel 1: fused two-MLP response.
// resp[e][s] = mask[e] * (x[e]@Wa1+ba1 relu @Wa2+ba2)[s] * sigmoid((...p...)[s])
// CTA tile: 128 electrons x 64 sensors, K=HID=128 in chunks of 16 via smem.
// ---------------------------------------------------------------------------
__global__ __launch_bounds__(256, 2)
void mlp_resp_kernel(const float* __restrict__ x,
                     const float* __restrict__ maskv,
                     const float* __restrict__ Wp1, const float* __restrict__ bp1,
                     const float* __restrict__ Wp2, const float* __restrict__ bp2,
                     const float* __restrict__ Wa1, const float* __restrict__ ba1,
                     const float* __restrict__ Wa2, const float* __restrict__ ba2,
                     int ne)
{
    __shared__ __align__(16) float xs[128][4];          // x0,x1,x2,mask
    __shared__ __align__(16) float W1s[2][3][HID_DIM];  // [p/a][f][h]
    __shared__ __align__(16) float b1s[2][HID_DIM];
    __shared__ __align__(16) float Hs[2][16][128];      // [p/a][k][electron]
    __shared__ __align__(16) float Ws[2][16][64];       // [p/a][k][sensor]

    const int tid = threadIdx.x;
    const int e0 = blockIdx.x * 128;
    const int s0 = blockIdx.y * 64;

    for (int i = tid; i < 3 * HID_DIM; i += 256) {
        (&W1s[0][0][0])[i] = Wp1[i];
        (&W1s[1][0][0])[i] = Wa1[i];
    }
    for (int i = tid; i < HID_DIM; i += 256) {
        b1s[0][i] = bp1[i];
        b1s[1][i] = ba1[i];
    }
    for (int i = tid; i < 128; i += 256) {
        int e = e0 + i;
        if (e < ne) {
            xs[i][0] = x[e * 3 + 0];
            xs[i][1] = x[e * 3 + 1];
            xs[i][2] = x[e * 3 + 2];
            xs[i][3] = maskv[e];
        } else {
            xs[i][0] = 0.f; xs[i][1] = 0.f; xs[i][2] = 0.f; xs[i][3] = 0.f;
        }
    }
    __syncthreads();

    float accp[8][4], acca[8][4];
#pragma unroll
    for (int u = 0; u < 8; u++)
#pragma unroll
        for (int v = 0; v < 4; v++) { accp[u][v] = 0.f; acca[u][v] = 0.f; }

    const int tm = tid >> 4;   // 0..15 -> 8 electron rows each
    const int tn = tid & 15;   // 0..15 -> 4 sensor cols each

    for (int k0 = 0; k0 < HID_DIM; k0 += 16) {
        // stage W2 chunk [16][64] for both MLPs (one float4 per thread per MLP)
        {
            int row = tid >> 4, c4 = tid & 15;
            *(float4*)&Ws[0][row][c4 * 4] =
                *(const float4*)&Wp2[(size_t)(k0 + row) * S_DIM + s0 + c4 * 4];
            *(float4*)&Ws[1][row][c4 * 4] =
                *(const float4*)&Wa2[(size_t)(k0 + row) * S_DIM + s0 + c4 * 4];
        }
        // compute hidden chunk [2][16][128] = 4096 entries, 16 per thread
#pragma unroll
        for (int r = 0; r < 16; r++) {
            int idx = tid + 256 * r;
            int m  = idx >> 11;          // 0: prob, 1: amp
            int kk = (idx >> 7) & 15;
            int el = idx & 127;
            float h = b1s[m][k0 + kk]
                    + xs[el][0] * W1s[m][0][k0 + kk]
                    + xs[el][1] * W1s[m][1][k0 + kk]
                    + xs[el][2] * W1s[m][2][k0 + kk];
            Hs[m][kk][el] = fmaxf(h, 0.f);
        }
        __syncthreads();

#pragma unroll
        for (int k = 0; k < 16; k++) {
            float4 hp0 = *(const float4*)&Hs[0][k][tm * 8];
            float4 hp1 = *(const float4*)&Hs[0][k][tm * 8 + 4];
            float4 ha0 = *(const float4*)&Hs[1][k][tm * 8];
            float4 ha1 = *(const float4*)&Hs[1][k][tm * 8 + 4];
            float4 wp  = *(const float4*)&Ws[0][k][tn * 4];
            float4 wa  = *(const float4*)&Ws[1][k][tn * 4];
            float hp[8] = {hp0.x, hp0.y, hp0.z, hp0.w, hp1.x, hp1.y, hp1.z, hp1.w};
            float ha[8] = {ha0.x, ha0.y, ha0.z, ha0.w, ha1.x, ha1.y, ha1.z, ha1.w};
            float wpv[4] = {wp.x, wp.y, wp.z, wp.w};
            float wav[4] = {wa.x, wa.y, wa.z, wa.w};
#pragma unroll
            for (int u = 0; u < 8; u++)
#pragma unroll
                for (int v = 0; v < 4; v++) {
                    accp[u][v] = fmaf(hp[u], wpv[v], accp[u][v]);
                    acca[u][v] = fmaf(ha[u], wav[v], acca[u][v]);
                }
        }
        __syncthreads();
    }

    float4 b2p = *(const float4*)&bp2[s0 + tn * 4];
    float4 b2a = *(const float4*)&ba2[s0 + tn * 4];
    float bpv[4] = {b2p.x, b2p.y, b2p.z, b2p.w};
    float bav[4] = {b2a.x, b2a.y, b2a.z, b2a.w};

#pragma unroll
    for (int u = 0; u < 8; u++) {
        int el = tm * 8 + u;
        int e = e0 + el;
        if (e < ne) {
            float mk = xs[el][3];
            float pv[4];
#pragma unroll
            for (int v = 0; v < 4; v++) {
                float p = accp[u][v] + bpv[v];
                float a = acca[u][v] + bav[v];
                pv[v] = a * mk * (1.0f / (1.0f + expf(-p)));
            }
            float4 o; o.x = pv[0]; o.y = pv[1]; o.z = pv[2]; o.w = pv[3];
            *(float4*)&g_resp[(size_t)e * S_DIM + s0 + tn * 4] = o;
        }
    }
}

// ---------------------------------------------------------------------------
// Kernel 2: banded scatter-GEMM.
// Each CTA owns a (64 s x 128 t) output tile of one K-split partial.
// Scans its electron range, compacts electrons whose Gaussian band overlaps
// the t-tile (deterministic, index-ordered), rank-1 accumulates in registers.
// ---------------------------------------------------------------------------
__global__ __launch_bounds__(256, 2)
void scatter_kernel(const float* __restrict__ zpos, const float* __restrict__ sig,
                    int ne)
{
    const int s0 = blockIdx.x * 64;
    const int t0 = blockIdx.y * 128;
    const int zp = blockIdx.z;
    const int tid = threadIdx.x;

    const float sigma  = sig[0];
    const float inv2s2 = 1.0f / (2.0f * sigma * sigma);
    const float coef   = 0.3989422804f / sqrtf(sigma * sigma);
    const float rad    = sqrtf(30.0f / inv2s2);      // exp(-30) cutoff ~9e-14
    const float lo = (float)t0 - rad;
    const float hi = (float)(t0 + 127) + rad;

    const int half = (ne + KSPLIT - 1) / KSPLIT;
    const int eBeg = zp * half;
    const int eEnd = (eBeg + half < ne) ? (eBeg + half) : ne;

    __shared__ __align__(16) int   list[256];
    __shared__ __align__(16) float zl[256];
    __shared__ int   wbase[8];
    __shared__ int   cnts;
    __shared__ __align__(16) float respS[16][64];
    __shared__ __align__(16) float gS[16][128];

    float acc[4][8];
#pragma unroll
    for (int u = 0; u < 4; u++)
#pragma unroll
        for (int v = 0; v < 8; v++) acc[u][v] = 0.f;

    const int si = tid >> 4;   // 0..15 -> 4 sensor rows each
    const int tj = tid & 15;   // 0..15 -> 8 tick cols each

    for (int cb = eBeg; cb < eEnd; cb += 256) {
        int e = cb + tid;
        float z = -1e30f;
        bool keep = false;
        if (e < eEnd) {
            z = zpos[e];
            keep = (z > lo) && (z < hi);
        }
        unsigned bm = __ballot_sync(0xffffffffu, keep);
        int lane = tid & 31, w = tid >> 5;
        if (lane == 0) wbase[w] = __popc(bm);
        __syncthreads();
        if (tid == 0) {
            int srun = 0;
#pragma unroll
            for (int q = 0; q < 8; q++) { int c = wbase[q]; wbase[q] = srun; srun += c; }
            cnts = srun;
        }
        __syncthreads();
        if (keep) {
            int p = wbase[w] + __popc(bm & ((1u << lane) - 1u));
            list[p] = e;
            zl[p] = z;
        }
        __syncthreads();
        int cnt = cnts;

        for (int g0 = 0; g0 < cnt; g0 += 16) {
            int gn = (cnt - g0 < 16) ? (cnt - g0) : 16;
            // stage resp slice [gn][64]: one float4 per thread
            {
                int eL = tid >> 4, c4 = tid & 15;
                float4 v = make_float4(0.f, 0.f, 0.f, 0.f);
                if (eL < gn)
                    v = *(const float4*)&g_resp[(size_t)list[g0 + eL] * S_DIM + s0 + c4 * 4];
                *(float4*)&respS[eL][c4 * 4] = v;
            }
            // compute Gaussian values [gn][128]: 8 per thread
            {
                int eL = tid >> 4;
                float zv = (eL < gn) ? zl[g0 + eL] : 0.f;
                int tb = t0 + (tid & 15) * 8;
#pragma unroll
                for (int r = 0; r < 8; r++) {
                    float d = (float)(tb + r) - zv;
                    float gv = (eL < gn) ? coef * expf(-d * d * inv2s2) : 0.f;
                    gS[eL][(tid & 15) * 8 + r] = gv;
                }
            }
            __syncthreads();

            for (int eL = 0; eL < gn; eL++) {
                float4 rv  = *(const float4*)&respS[eL][si * 4];
                float4 g0v = *(const float4*)&gS[eL][tj * 8];
                float4 g1v = *(const float4*)&gS[eL][tj * 8 + 4];
                float rr[4] = {rv.x, rv.y, rv.z, rv.w};
                float gg[8] = {g0v.x, g0v.y, g0v.z, g0v.w, g1v.x, g1v.y, g1v.z, g1v.w};
#pragma unroll
                for (int u = 0; u < 4; u++)
#pragma unroll
                    for (int v = 0; v < 8; v++)
                        acc[u][v] = fmaf(rr[u], gg[v], acc[u][v]);
            }
            __syncthreads();
        }
    }

#pragma unroll
    for (int u = 0; u < 4; u++) {
        int s = s0 + si * 4 + u;
        float* dst = &g_part[((size_t)zp * S_DIM + s) * T_DIM + t0 + tj * 8];
        float4 o0 = make_float4(acc[u][0], acc[u][1], acc[u][2], acc[u][3]);
        float4 o1 = make_float4(acc[u][4], acc[u][5], acc[u][6], acc[u][7]);
        *(float4*)&dst[0] = o0;
        *(float4*)&dst[4] = o1;
    }
}

// ---------------------------------------------------------------------------
// Kernel 3: reduce K-split partials into d_out.
// ---------------------------------------------------------------------------
__global__ void reduce_kernel(float* __restrict__ out)
{
    int idx = blockIdx.x * 256 + threadIdx.x;   // float4 index, exact coverage
    const float4* a = (const float4*)g_part;
    const float4* b = (const float4*)(g_part + (size_t)S_DIM * T_DIM);
    float4 va = a[idx], vb = b[idx];
    ((float4*)out)[idx] = make_float4(va.x + vb.x, va.y + vb.y,
                                      va.z + vb.z, va.w + vb.w);
}

// ---------------------------------------------------------------------------
extern "C" void kernel_launch(void* const* d_in, const int* in_sizes, int n_in,
                              void* d_out, int out_size)
{
    const float* x    = (const float*)d_in[0];
    const float* zpos = (const float*)d_in[1];
    const float* mask = (const float*)d_in[2];
    const float* Wp1  = (const float*)d_in[3];
    const float* bp1  = (const float*)d_in[4];
    const float* Wp2  = (const float*)d_in[5];
    const float* bp2  = (const float*)d_in[6];
    const float* Wa1  = (const float*)d_in[7];
    const float* ba1  = (const float*)d_in[8];
    const float* Wa2  = (const float*)d_in[9];
    const float* ba2  = (const float*)d_in[10];
    const float* sig  = (const float*)d_in[11];

    int ne = in_sizes[1];          // z_positions element count = B*N
    if (ne > NE_MAX) ne = NE_MAX;

    dim3 g1((ne + 127) / 128, S_DIM / 64);
    mlp_resp_kernel<<<g1, 256>>>(x, mask, Wp1, bp1, Wp2, bp2,
                                 Wa1, ba1, Wa2, ba2, ne);

    dim3 g2(S_DIM / 64, T_DIM / 128, KSPLIT);
    scatter_kernel<<<g2, 256>>>(zpos, sig, ne);

    reduce_kernel<<<(S_DIM * T_DIM / 4) / 256, 256>>>((float*)d_out);
}

// round 3
// speedup vs baseline: 1.5648x; 1.5648x over previous
#include <cuda_runtime.h>
#include <math.h>

#define S_DIM 1024
#define T_DIM 1024
#define HID_DIM 128
#define NE_MAX 32000
#define NBUCKET 17          // tap-column buckets of width 64 covering c in [0,1088)
#define BCAP 4096           // electrons per bucket (mean ~2160, 40 sigma margin)
#define RMAX 72             // max conv half-width (sigma up to ~9)

// Scratch (__device__ globals; 16B aligned where float4-accessed)
__device__ __align__(16) float g_resp[(size_t)NE_MAX * S_DIM];    // [e][s]
__device__ __align__(16) float g_D[(size_t)NBUCKET * 64 * S_DIM]; // [c][s], c = tau+2
__device__ int   g_bcnt[NBUCKET];
__device__ int   g_bidx[NBUCKET * BCAP];
__device__ float g_bz[NBUCKET * BCAP];

// ---------------------------------------------------------------------------
// Kernel 0: bucket electrons by tap-column range (deterministic, index order).
// Electron with k = floor(z) has taps c = k..k+5. Bucket b holds electrons
// with k in [64b-5, 64b+63]  <=>  z in [64b-5, 64b+64).
// ---------------------------------------------------------------------------
__global__ void bucket_kernel(const float* __restrict__ zpos, int ne)
{
    const int b = blockIdx.x;
    const int tid = threadIdx.x;
    const float lob = (float)(b * 64 - 5);
    const float hib = (float)(b * 64 + 64);

    __shared__ int wsum[8];
    __shared__ int base;
    if (tid == 0) base = 0;
    __syncthreads();

    for (int cb = 0; cb < ne; cb += 256) {
        int e = cb + tid;
        float z = 0.f;
        bool keep = false;
        if (e < ne) {
            z = zpos[e];
            keep = (z >= lob) && (z < hib);
        }
        unsigned bm = __ballot_sync(0xffffffffu, keep);
        int lane = tid & 31, w = tid >> 5;
        if (lane == 0) wsum[w] = __popc(bm);
        __syncthreads();
        if (tid == 0) {
            int s = base;
#pragma unroll
            for (int q = 0; q < 8; q++) { int t = wsum[q]; wsum[q] = s; s += t; }
            base = s;
        }
        __syncthreads();
        if (keep) {
            int p = wsum[w] + __popc(bm & ((1u << lane) - 1u));
            if (p < BCAP) {
                g_bidx[b * BCAP + p] = e;
                g_bz[b * BCAP + p] = z;
            }
        }
        __syncthreads();
    }
    if (tid == 0) g_bcnt[b] = (base < BCAP) ? base : BCAP;
}

// ---------------------------------------------------------------------------
// Kernel 1: fused two-MLP response -> g_resp[e][s].
// CTA: 128 threads, tile 64 electrons x 128 sensors, both MLPs.
// Thread tile 8e x 8s x 2 mlps (128 accumulators). K=128 staged in 16-chunks.
// ---------------------------------------------------------------------------
__global__ __launch_bounds__(128, 2)
void mlp_resp_kernel(const float* __restrict__ x,
                     const float* __restrict__ maskv,
                     const float* __restrict__ Wp1, const float* __restrict__ bp1,
                     const float* __restrict__ Wp2, const float* __restrict__ bp2,
                     const float* __restrict__ Wa1, const float* __restrict__ ba1,
                     const float* __restrict__ Wa2, const float* __restrict__ ba2,
                     int ne)
{
    __shared__ __align__(16) float xs[64][4];
    __shared__ __align__(16) float W1s[2][3][HID_DIM];
    __shared__ __align__(16) float b1s[2][HID_DIM];
    __shared__ __align__(16) float Hs[2][16][64];
    __shared__ __align__(16) float Ws[2][16][128];

    const int tid = threadIdx.x;
    const int e0 = blockIdx.x * 64;
    const int s0 = blockIdx.y * 128;

    for (int i = tid; i < 3 * HID_DIM; i += 128) {
        (&W1s[0][0][0])[i] = Wp1[i];
        (&W1s[1][0][0])[i] = Wa1[i];
    }
    {
        b1s[0][tid] = bp1[tid];
        b1s[1][tid] = ba1[tid];
    }
    if (tid < 64) {
        int e = e0 + tid;
        if (e < ne) {
            xs[tid][0] = x[e * 3 + 0];
            xs[tid][1] = x[e * 3 + 1];
            xs[tid][2] = x[e * 3 + 2];
            xs[tid][3] = maskv[e];
        } else {
            xs[tid][0] = 0.f; xs[tid][1] = 0.f; xs[tid][2] = 0.f; xs[tid][3] = 0.f;
        }
    }
    __syncthreads();

    float accp[8][8], acca[8][8];
#pragma unroll
    for (int u = 0; u < 8; u++)
#pragma unroll
        for (int v = 0; v < 8; v++) { accp[u][v] = 0.f; acca[u][v] = 0.f; }

    const int tm = tid >> 4;   // 0..7  -> 8 electron rows each
    const int tn = tid & 15;   // 0..15 -> 8 sensor cols each

    for (int k0 = 0; k0 < HID_DIM; k0 += 16) {
        // stage W2 chunk: 2 x [16][128] = 1024 float4, 8 per thread
#pragma unroll
        for (int r = 0; r < 8; r++) {
            int i = r * 128 + tid;
            int m = i >> 9, row = (i >> 5) & 15, c4 = i & 31;
            const float* W2 = m ? Wa2 : Wp2;
            *(float4*)&Ws[m][row][c4 * 4] =
                *(const float4*)&W2[(size_t)(k0 + row) * S_DIM + s0 + c4 * 4];
        }
        // hidden chunk: 2 x [16][64] = 2048 entries, 16 per thread
#pragma unroll
        for (int r = 0; r < 16; r++) {
            int i = r * 128 + tid;
            int m = i >> 10, kk = (i >> 6) & 15, el = i & 63;
            float h = b1s[m][k0 + kk]
                    + xs[el][0] * W1s[m][0][k0 + kk]
                    + xs[el][1] * W1s[m][1][k0 + kk]
                    + xs[el][2] * W1s[m][2][k0 + kk];
            Hs[m][kk][el] = fmaxf(h, 0.f);
        }
        __syncthreads();

#pragma unroll
        for (int k = 0; k < 16; k++) {
            float4 hp0 = *(const float4*)&Hs[0][k][tm * 8];
            float4 hp1 = *(const float4*)&Hs[0][k][tm * 8 + 4];
            float4 ha0 = *(const float4*)&Hs[1][k][tm * 8];
            float4 ha1 = *(const float4*)&Hs[1][k][tm * 8 + 4];
            float4 wp0 = *(const float4*)&Ws[0][k][tn * 8];
            float4 wp1 = *(const float4*)&Ws[0][k][tn * 8 + 4];
            float4 wa0 = *(const float4*)&Ws[1][k][tn * 8];
            float4 wa1 = *(const float4*)&Ws[1][k][tn * 8 + 4];
            float hp[8] = {hp0.x, hp0.y, hp0.z, hp0.w, hp1.x, hp1.y, hp1.z, hp1.w};
            float ha[8] = {ha0.x, ha0.y, ha0.z, ha0.w, ha1.x, ha1.y, ha1.z, ha1.w};
            float wp[8] = {wp0.x, wp0.y, wp0.z, wp0.w, wp1.x, wp1.y, wp1.z, wp1.w};
            float wa[8] = {wa0.x, wa0.y, wa0.z, wa0.w, wa1.x, wa1.y, wa1.z, wa1.w};
#pragma unroll
            for (int u = 0; u < 8; u++)
#pragma unroll
                for (int v = 0; v < 8; v++) {
                    accp[u][v] = fmaf(hp[u], wp[v], accp[u][v]);
                    acca[u][v] = fmaf(ha[u], wa[v], acca[u][v]);
                }
        }
        __syncthreads();
    }

    float bpv[8], bav[8];
    {
        float4 p0 = *(const float4*)&bp2[s0 + tn * 8];
        float4 p1 = *(const float4*)&bp2[s0 + tn * 8 + 4];
        float4 a0 = *(const float4*)&ba2[s0 + tn * 8];
        float4 a1 = *(const float4*)&ba2[s0 + tn * 8 + 4];
        bpv[0]=p0.x; bpv[1]=p0.y; bpv[2]=p0.z; bpv[3]=p0.w;
        bpv[4]=p1.x; bpv[5]=p1.y; bpv[6]=p1.z; bpv[7]=p1.w;
        bav[0]=a0.x; bav[1]=a0.y; bav[2]=a0.z; bav[3]=a0.w;
        bav[4]=a1.x; bav[5]=a1.y; bav[6]=a1.z; bav[7]=a1.w;
    }

#pragma unroll
    for (int u = 0; u < 8; u++) {
        int el = tm * 8 + u;
        int e = e0 + el;
        if (e < ne) {
            float mk = xs[el][3];
            float pv[8];
#pragma unroll
            for (int v = 0; v < 8; v++) {
                float p = accp[u][v] + bpv[v];
                float a = acca[u][v] + bav[v];
                pv[v] = a * mk * (1.0f / (1.0f + expf(-p)));
            }
            float* dst = &g_resp[(size_t)e * S_DIM + s0 + tn * 8];
            *(float4*)&dst[0] = make_float4(pv[0], pv[1], pv[2], pv[3]);
            *(float4*)&dst[4] = make_float4(pv[4], pv[5], pv[6], pv[7]);
        }
    }
}

// ---------------------------------------------------------------------------
// Kernel 2 (stage A): tap scatter. D[c][s] = sum_e resp[e,s] * w_j(f_e),
// c = floor(z_e) + j, j in 0..5 (6-point Lagrange stencil, nodes -2..3).
// CTA: (s-tile 64) x (bucket b). 128 threads = 2 groups of 64 s-lanes, each
// with a private smem D copy; reduced at the end. Fully deterministic.
// ---------------------------------------------------------------------------
__global__ __launch_bounds__(128)
void stageA_kernel()
{
    const int s0 = blockIdx.x * 64;
    const int b  = blockIdx.y;
    const int tid = threadIdx.x;
    const int grp = tid >> 6;       // 0,1
    const int sl  = tid & 63;

    __shared__ float Dg[2][64][64];     // 32 KB
    __shared__ float wch[128][6];
    __shared__ int   ech[128];
    __shared__ int   kch[128];

    for (int i = tid; i < 2 * 64 * 64; i += 128)
        (&Dg[0][0][0])[i] = 0.f;
    __syncthreads();

    const int cnt = g_bcnt[b];
    const int c0 = b * 64;

    for (int base = 0; base < cnt; base += 128) {
        int n = cnt - base; if (n > 128) n = 128;
        if (tid < n) {
            float z = g_bz[b * BCAP + base + tid];
            float kf = floorf(z);
            float f = z - kf;
            float t0 = f + 2.f, t1 = f + 1.f, t2 = f, t3 = f - 1.f,
                  t4 = f - 2.f, t5 = f - 3.f;
            wch[tid][0] = t1 * t2 * t3 * t4 * t5 * (-1.f / 120.f);
            wch[tid][1] = t0 * t2 * t3 * t4 * t5 * ( 1.f /  24.f);
            wch[tid][2] = t0 * t1 * t3 * t4 * t5 * (-1.f /  12.f);
            wch[tid][3] = t0 * t1 * t2 * t4 * t5 * ( 1.f /  12.f);
            wch[tid][4] = t0 * t1 * t2 * t3 * t5 * (-1.f /  24.f);
            wch[tid][5] = t0 * t1 * t2 * t3 * t4 * ( 1.f / 120.f);
            kch[tid] = (int)kf;
            ech[tid] = g_bidx[b * BCAP + base + tid];
        }
        __syncthreads();

        for (int i = grp; i < n; i += 2) {
            int e = ech[i];
            int cl0 = kch[i] - c0;
            float r = g_resp[(size_t)e * S_DIM + s0 + sl];
#pragma unroll
            for (int j = 0; j < 6; j++) {
                int cl = cl0 + j;
                if (cl >= 0 && cl < 64)
                    Dg[grp][cl][sl] += r * wch[i][j];
            }
        }
        __syncthreads();
    }

    for (int idx = tid; idx < 4096; idx += 128) {
        int cl = idx >> 6, s2 = idx & 63;
        float v = Dg[0][cl][s2] + Dg[1][cl][s2];
        g_D[(size_t)(c0 + cl) * S_DIM + s0 + s2] = v;
    }
}

// ---------------------------------------------------------------------------
// Kernel 3: banded 1-D convolution out[s,t] = sum_tau D[tau,s]*G(t-tau).
// CTA tile: 64 s x 32 t. D slab staged in smem; G table in smem.
// ---------------------------------------------------------------------------
__global__ __launch_bounds__(256)
void conv_kernel(const float* __restrict__ sig, float* __restrict__ out)
{
    __shared__ float Db[2 * RMAX + 33][64];   // 45.3 KB
    __shared__ float Gs[2 * RMAX + 1];

    const int s0 = blockIdx.x * 64;
    const int t0 = blockIdx.y * 32;
    const int tid = threadIdx.x;

    const float sigma  = sig[0];
    const float inv2s2 = 1.0f / (2.0f * sigma * sigma);
    const float coef   = 0.3989422804f / sqrtf(sigma * sigma);
    int R = (int)ceilf(sigma * 7.746f);       // exp(-30) cutoff
    if (R < 1) R = 1;
    if (R > RMAX) R = RMAX;
    const int nG = 2 * R + 1;
    const int rows = 2 * R + 33;
    const int rlo = t0 - R + 2;               // D column index of row 0

    for (int i = tid; i < nG; i += 256) {
        float d = (float)(i - R);
        Gs[i] = coef * expf(-d * d * inv2s2);
    }
    for (int idx = tid; idx < rows * 64; idx += 256) {
        int ri = idx >> 6, s2 = idx & 63;
        int c = rlo + ri;
        Db[ri][s2] = (c >= 0 && c < T_DIM + 4) ?
            g_D[(size_t)c * S_DIM + s0 + s2] : 0.f;
    }
    __syncthreads();

    const int sl = tid & 31;        // handles s0+sl and s0+sl+32
    const int tq = tid >> 5;        // 0..7, t = t0 + tq*4 + k
    const int tb = tq * 4;

    float acc0[4] = {0.f, 0.f, 0.f, 0.f};
    float acc1[4] = {0.f, 0.f, 0.f, 0.f};

    for (int ri = 0; ri < rows; ri++) {
        float v0 = Db[ri][sl];
        float v1 = Db[ri][sl + 32];
#pragma unroll
        for (int k = 0; k < 4; k++) {
            int gi = ri - tb - k;
            if (gi >= 0 && gi < nG) {
                float w = Gs[gi];
                acc0[k] = fmaf(v0, w, acc0[k]);
                acc1[k] = fmaf(v1, w, acc1[k]);
            }
        }
    }

    *(float4*)&out[(size_t)(s0 + sl) * T_DIM + t0 + tb] =
        make_float4(acc0[0], acc0[1], acc0[2], acc0[3]);
    *(float4*)&out[(size_t)(s0 + sl + 32) * T_DIM + t0 + tb] =
        make_float4(acc1[0], acc1[1], acc1[2], acc1[3]);
}

// ---------------------------------------------------------------------------
extern "C" void kernel_launch(void* const* d_in, const int* in_sizes, int n_in,
                              void* d_out, int out_size)
{
    const float* x    = (const float*)d_in[0];
    const float* zpos = (const float*)d_in[1];
    const float* mask = (const float*)d_in[2];
    const float* Wp1  = (const float*)d_in[3];
    const float* bp1  = (const float*)d_in[4];
    const float* Wp2  = (const float*)d_in[5];
    const float* bp2  = (const float*)d_in[6];
    const float* Wa1  = (const float*)d_in[7];
    const float* ba1  = (const float*)d_in[8];
    const float* Wa2  = (const float*)d_in[9];
    const float* ba2  = (const float*)d_in[10];
    const float* sig  = (const float*)d_in[11];

    int ne = in_sizes[1];
    if (ne > NE_MAX) ne = NE_MAX;

    bucket_kernel<<<NBUCKET, 256>>>(zpos, ne);

    dim3 g1((ne + 63) / 64, S_DIM / 128);
    mlp_resp_kernel<<<g1, 128>>>(x, mask, Wp1, bp1, Wp2, bp2,
                                 Wa1, ba1, Wa2, ba2, ne);

    dim3 g2(S_DIM / 64, NBUCKET);
    stageA_kernel<<<g2, 128>>>();

    dim3 g3(S_DIM / 64, T_DIM / 32);
    conv_kernel<<<g3, 256>>>(sig, (float*)d_out);
}

// round 6
// speedup vs baseline: 4.1947x; 2.6807x over previous
#include <cuda_runtime.h>
#include <cuda_bf16.h>
#include <math.h>
#include <stdint.h>

#define S_DIM 1024
#define T_DIM 1024
#define HID_DIM 128
#define NE_MAX 32000
#define NBUCKET 17
#define BCAP 4096
#define RMAX 72
#define NSTILE 8
#define EGRP 18
#define BTILE 34816u        // one [128][136] bf16 tile in bytes
#define LDT 136             // padded row length (bf16 elems)

// ---------------- scratch (__device__ globals) ----------------
__device__ __align__(16) float g_resp[(size_t)NE_MAX * S_DIM];     // [e][s]
__device__ __align__(16) float g_D[(size_t)NBUCKET * 64 * S_DIM];  // [c][s]
__device__ int   g_bcnt[NBUCKET];
__device__ int   g_bidx[NBUCKET * BCAP];
__device__ float g_bz[NBUCKET * BCAP];
// bf16 weight tiles [stile][p_hi,p_lo,a_hi,a_lo][128k][136n]
__device__ __align__(16) unsigned char g_Bprep[(size_t)NSTILE * 4 * BTILE];

// ---------------- helpers ----------------
__device__ __forceinline__ uint32_t smem_u32(const void* p) {
    uint32_t a;
    asm("{ .reg .u64 t; cvta.to.shared.u64 t, %1; cvt.u32.u64 %0, t; }"
        : "=r"(a) : "l"(p));
    return a;
}
__device__ __forceinline__ void ldsm_x4(uint32_t* r, uint32_t addr) {
    asm volatile("ldmatrix.sync.aligned.m8n8.x4.shared.b16 {%0,%1,%2,%3}, [%4];"
                 : "=r"(r[0]), "=r"(r[1]), "=r"(r[2]), "=r"(r[3]) : "r"(addr));
}
__device__ __forceinline__ void ldsm_x4_t(uint32_t* r, uint32_t addr) {
    asm volatile("ldmatrix.sync.aligned.m8n8.x4.trans.shared.b16 {%0,%1,%2,%3}, [%4];"
                 : "=r"(r[0]), "=r"(r[1]), "=r"(r[2]), "=r"(r[3]) : "r"(addr));
}
__device__ __forceinline__ void mma_bf16(float* c, const uint32_t* a, const uint32_t* b) {
    asm volatile("mma.sync.aligned.m16n8k16.row.col.f32.bf16.bf16.f32 "
                 "{%0,%1,%2,%3}, {%4,%5,%6,%7}, {%8,%9}, {%0,%1,%2,%3};"
                 : "+f"(c[0]), "+f"(c[1]), "+f"(c[2]), "+f"(c[3])
                 : "r"(a[0]), "r"(a[1]), "r"(a[2]), "r"(a[3]), "r"(b[0]), "r"(b[1]));
}

// ---------------------------------------------------------------------------
// Prep: split W2 into bf16 hi/lo tiles [k][136] row-major.
// which: 0=p_hi 1=p_lo 2=a_hi 3=a_lo
// ---------------------------------------------------------------------------
__global__ void prep_kernel(const float* __restrict__ Wp2, const float* __restrict__ Wa2)
{
    const int stile = blockIdx.x, which = blockIdx.y;
    const int s0 = stile * 128;
    const float* W2 = (which >= 2) ? Wa2 : Wp2;
    const int split = which & 1;
    __nv_bfloat16* dst = (__nv_bfloat16*)(g_Bprep + ((size_t)stile * 4 + which) * BTILE);
    for (int idx = threadIdx.x; idx < 128 * 128; idx += 256) {
        int k = idx >> 7, n = idx & 127;
        float w = W2[(size_t)k * S_DIM + s0 + n];
        __nv_bfloat16 hi = __float2bfloat16(w);
        __nv_bfloat16 v = split ? __float2bfloat16(w - __bfloat162float(hi)) : hi;
        dst[k * LDT + n] = v;
    }
}

// ---------------------------------------------------------------------------
// Bucket electrons (deterministic, index order), 4 per thread per round.
// ---------------------------------------------------------------------------
__global__ void bucket_kernel(const float* __restrict__ zpos, int ne)
{
    const int b = blockIdx.x;
    const int tid = threadIdx.x;
    const float lob = (float)(b * 64 - 5);
    const float hib = (float)(b * 64 + 64);

    __shared__ int wsum[4][8];
    __shared__ int base0;
    if (tid == 0) base0 = 0;
    __syncthreads();

    const int lane = tid & 31, w = tid >> 5;
    for (int cb = 0; cb < ne; cb += 1024) {
        float z[4]; bool kp[4]; unsigned bm[4];
#pragma unroll
        for (int q = 0; q < 4; q++) {
            int e = cb + q * 256 + tid;
            kp[q] = false; z[q] = 0.f;
            if (e < ne) { z[q] = zpos[e]; kp[q] = (z[q] >= lob) && (z[q] < hib); }
        }
#pragma unroll
        for (int q = 0; q < 4; q++) bm[q] = __ballot_sync(0xffffffffu, kp[q]);
        if (lane == 0)
#pragma unroll
            for (int q = 0; q < 4; q++) wsum[q][w] = __popc(bm[q]);
        __syncthreads();
        if (tid == 0) {
            int run = base0;
#pragma unroll
            for (int q = 0; q < 4; q++)
#pragma unroll
                for (int ww = 0; ww < 8; ww++) {
                    int t = wsum[q][ww]; wsum[q][ww] = run; run += t;
                }
            base0 = run;
        }
        __syncthreads();
#pragma unroll
        for (int q = 0; q < 4; q++) {
            if (kp[q]) {
                int p = wsum[q][w] + __popc(bm[q] & ((1u << lane) - 1u));
                if (p < BCAP) {
                    g_bidx[b * BCAP + p] = cb + q * 256 + tid;
                    g_bz[b * BCAP + p] = z[q];
                }
            }
        }
        __syncthreads();
    }
    if (tid == 0) g_bcnt[b] = (base0 < BCAP) ? base0 : BCAP;
}

// ---------------------------------------------------------------------------
// MLP via mma.sync bf16. Grid (NSTILE=8, EGRP=18), 256 threads / 8 warps.
// CTA: 128-sensor tile, B (4 weight tiles) resident; loops 128-electron tiles.
// Warp tile 32e x 64s (warps: 4 over e, 2 over s).
// ---------------------------------------------------------------------------
__global__ __launch_bounds__(256, 1)
void mlp_mma_kernel(const float* __restrict__ x, const float* __restrict__ maskv,
                    const float* __restrict__ Wp1, const float* __restrict__ bp1,
                    const float* __restrict__ bp2,
                    const float* __restrict__ Wa1, const float* __restrict__ ba1,
                    const float* __restrict__ ba2,
                    int ne)
{
    extern __shared__ __align__(16) unsigned char dyn[];
    __shared__ __align__(16) float xs[128][4];
    __shared__ __align__(16) float W1s[2][3][HID_DIM];
    __shared__ __align__(16) float b1s[2][HID_DIM];
    __shared__ __align__(16) float bb[2][128];

    const int tid = threadIdx.x;
    const int wid = tid >> 5, lane = tid & 31;
    const int wy = wid >> 1;          // 0..3 over electrons
    const int wx = wid & 1;           // 0..1 over sensors
    const int stile = blockIdx.x, gy = blockIdx.y;
    const int s0 = stile * 128;
    const int ntiles = (ne + 127) / 128;

    unsigned char* Ap = dyn;
    unsigned char* Aa = dyn + BTILE;
    unsigned char* Bt = dyn + 2 * BTILE;

    // persistent staging
    for (int i = tid; i < 3 * HID_DIM; i += 256) {
        (&W1s[0][0][0])[i] = Wp1[i];
        (&W1s[1][0][0])[i] = Wa1[i];
    }
    for (int i = tid; i < HID_DIM; i += 256) {
        b1s[0][i] = bp1[i];
        b1s[1][i] = ba1[i];
        bb[0][i] = bp2[s0 + i];
        bb[1][i] = ba2[s0 + i];
    }
    {
        const uint4* src = (const uint4*)(g_Bprep + (size_t)stile * 4 * BTILE);
        uint4* d4 = (uint4*)Bt;
        for (int i = tid; i < (int)(4 * BTILE / 16); i += 256) d4[i] = src[i];
    }
    __syncthreads();

    const uint32_t ApS = smem_u32(Ap), AaS = smem_u32(Aa), BtS = smem_u32(Bt);
    // ldmatrix per-lane offset (bytes): row = lane&15, col-block = (lane>>4)*8
    const uint32_t lmOff = (uint32_t)(lane & 15) * (LDT * 2) + (uint32_t)(lane >> 4) * 16;

    for (int et = gy; et < ntiles; et += EGRP) {
        const int e0 = et * 128;

        if (tid < 128) {
            int e = e0 + tid;
            if (e < ne) {
                xs[tid][0] = x[e * 3 + 0];
                xs[tid][1] = x[e * 3 + 1];
                xs[tid][2] = x[e * 3 + 2];
            } else {
                xs[tid][0] = 0.f; xs[tid][1] = 0.f; xs[tid][2] = 0.f;
            }
        }
        __syncthreads();   // also protects A tiles: all warps past previous mainloop

        // H (fp32) -> bf16 pairs into A tiles [el][k], row stride LDT
        for (int i = tid; i < 16384; i += 256) {
            int m = i >> 13, el = (i >> 6) & 127, k = (i & 63) * 2;
            float x0 = xs[el][0], x1 = xs[el][1], x2 = xs[el][2];
            float h0 = b1s[m][k]     + x0 * W1s[m][0][k]     + x1 * W1s[m][1][k]     + x2 * W1s[m][2][k];
            float h1 = b1s[m][k + 1] + x0 * W1s[m][0][k + 1] + x1 * W1s[m][1][k + 1] + x2 * W1s[m][2][k + 1];
            h0 = fmaxf(h0, 0.f); h1 = fmaxf(h1, 0.f);
            __nv_bfloat162 v = __floats2bfloat162_rn(h0, h1);
            unsigned char* base = m ? Aa : Ap;
            *(uint32_t*)(base + el * (LDT * 2) + k * 2) = *(uint32_t*)&v;
        }
        __syncthreads();

        float accP[2][8][4], accA[2][8][4];
#pragma unroll
        for (int mt = 0; mt < 2; mt++)
#pragma unroll
            for (int nt = 0; nt < 8; nt++)
#pragma unroll
                for (int j = 0; j < 4; j++) { accP[mt][nt][j] = 0.f; accA[mt][nt][j] = 0.f; }

#pragma unroll
        for (int sp = 0; sp < 2; sp++) {
            const uint32_t BpS = BtS + (uint32_t)sp * BTILE;
            const uint32_t BaS = BtS + (uint32_t)(2 + sp) * BTILE;
#pragma unroll
            for (int ks = 0; ks < 8; ks++) {
                const uint32_t kb = (uint32_t)ks * 32;            // k0*2 bytes
                const uint32_t krow = (uint32_t)ks * 16 * (LDT * 2);
                uint32_t a0[4], a1[4], bf[4][4];
                // ---- prob MLP ----
                ldsm_x4(a0, ApS + (uint32_t)(wy * 32) * (LDT * 2) + kb + lmOff);
                ldsm_x4(a1, ApS + (uint32_t)(wy * 32 + 16) * (LDT * 2) + kb + lmOff);
#pragma unroll
                for (int nb = 0; nb < 4; nb++)
                    ldsm_x4_t(bf[nb], BpS + krow + (uint32_t)(wx * 64 + nb * 16) * 2 + lmOff);
#pragma unroll
                for (int nb = 0; nb < 4; nb++) {
                    mma_bf16(accP[0][2 * nb],     a0, &bf[nb][0]);
                    mma_bf16(accP[0][2 * nb + 1], a0, &bf[nb][2]);
                    mma_bf16(accP[1][2 * nb],     a1, &bf[nb][0]);
                    mma_bf16(accP[1][2 * nb + 1], a1, &bf[nb][2]);
                }
                // ---- amp MLP ----
                ldsm_x4(a0, AaS + (uint32_t)(wy * 32) * (LDT * 2) + kb + lmOff);
                ldsm_x4(a1, AaS + (uint32_t)(wy * 32 + 16) * (LDT * 2) + kb + lmOff);
#pragma unroll
                for (int nb = 0; nb < 4; nb++)
                    ldsm_x4_t(bf[nb], BaS + krow + (uint32_t)(wx * 64 + nb * 16) * 2 + lmOff);
#pragma unroll
                for (int nb = 0; nb < 4; nb++) {
                    mma_bf16(accA[0][2 * nb],     a0, &bf[nb][0]);
                    mma_bf16(accA[0][2 * nb + 1], a0, &bf[nb][2]);
                    mma_bf16(accA[1][2 * nb],     a1, &bf[nb][0]);
                    mma_bf16(accA[1][2 * nb + 1], a1, &bf[nb][2]);
                }
            }
        }

        // epilogue straight from accumulators
        const int rbase = wy * 32 + (lane >> 2);
        const int colb = wx * 64 + (lane & 3) * 2;
#pragma unroll
        for (int mt = 0; mt < 2; mt++) {
            int ra = e0 + rbase + mt * 16;
            int rb = ra + 8;
            float mka = (ra < ne) ? maskv[ra] : 0.f;
            float mkb = (rb < ne) ? maskv[rb] : 0.f;
#pragma unroll
            for (int nt = 0; nt < 8; nt++) {
                int col = colb + nt * 8;
                float bp0 = bb[0][col], bp1v = bb[0][col + 1];
                float ba0 = bb[1][col], ba1v = bb[1][col + 1];
                float p0 = accP[mt][nt][0] + bp0, p1 = accP[mt][nt][1] + bp1v;
                float p2 = accP[mt][nt][2] + bp0, p3 = accP[mt][nt][3] + bp1v;
                float A0 = accA[mt][nt][0] + ba0, A1 = accA[mt][nt][1] + ba1v;
                float A2 = accA[mt][nt][2] + ba0, A3 = accA[mt][nt][3] + ba1v;
                float o0 = A0 * mka * (1.0f / (1.0f + expf(-p0)));
                float o1 = A1 * mka * (1.0f / (1.0f + expf(-p1)));
                float o2 = A2 * mkb * (1.0f / (1.0f + expf(-p2)));
                float o3 = A3 * mkb * (1.0f / (1.0f + expf(-p3)));
                if (ra < ne) *(float2*)&g_resp[(size_t)ra * S_DIM + s0 + col] = make_float2(o0, o1);
                if (rb < ne) *(float2*)&g_resp[(size_t)rb * S_DIM + s0 + col] = make_float2(o2, o3);
            }
        }
    }
}

// ---------------------------------------------------------------------------
// Stage A: tap scatter with 4-deep LDG batching. grid (32 s-tiles, 17 buckets).
// 128 threads = 4 warps, each with a private Dg slab (deterministic order).
// ---------------------------------------------------------------------------
__global__ __launch_bounds__(128)
void stageA_kernel()
{
    const int s0 = blockIdx.x * 32;
    const int b = blockIdx.y;
    const int tid = threadIdx.x;
    const int warp = tid >> 5, sl = tid & 31;

    __shared__ float Dg[4][64][32];
    __shared__ float wch[128][6];
    __shared__ int   ech[128];
    __shared__ int   kch[128];

    for (int i = tid; i < 4 * 64 * 32; i += 128) (&Dg[0][0][0])[i] = 0.f;
    __syncthreads();

    const int cnt = g_bcnt[b];
    const int c0 = b * 64;

    for (int base = 0; base < cnt; base += 128) {
        int n = cnt - base; if (n > 128) n = 128;
        if (tid < n) {
            float z = g_bz[b * BCAP + base + tid];
            float kf = floorf(z);
            float f = z - kf;
            float t0 = f + 2.f, t1 = f + 1.f, t2 = f, t3 = f - 1.f,
                  t4 = f - 2.f, t5 = f - 3.f;
            wch[tid][0] = t1 * t2 * t3 * t4 * t5 * (-1.f / 120.f);
            wch[tid][1] = t0 * t2 * t3 * t4 * t5 * ( 1.f /  24.f);
            wch[tid][2] = t0 * t1 * t3 * t4 * t5 * (-1.f /  12.f);
            wch[tid][3] = t0 * t1 * t2 * t4 * t5 * ( 1.f /  12.f);
            wch[tid][4] = t0 * t1 * t2 * t3 * t5 * (-1.f /  24.f);
            wch[tid][5] = t0 * t1 * t2 * t3 * t4 * ( 1.f / 120.f);
            kch[tid] = (int)kf;
            ech[tid] = g_bidx[b * BCAP + base + tid];
        }
        __syncthreads();

        for (int i0 = warp * 4; i0 < n; i0 += 16) {
            float r[4];
#pragma unroll
            for (int q = 0; q < 4; q++) {
                int i = i0 + q;
                r[q] = (i < n) ? g_resp[(size_t)ech[i] * S_DIM + s0 + sl] : 0.f;
            }
#pragma unroll
            for (int q = 0; q < 4; q++) {
                int i = i0 + q;
                if (i < n) {
                    int cl0 = kch[i] - c0;
#pragma unroll
                    for (int j = 0; j < 6; j++) {
                        int cl = cl0 + j;
                        if (cl >= 0 && cl < 64)
                            Dg[warp][cl][sl] += r[q] * wch[i][j];
                    }
                }
            }
        }
        __syncthreads();
    }

    for (int idx = tid; idx < 2048; idx += 128) {
        int cl = idx >> 5, s2 = idx & 31;
        float v = Dg[0][cl][s2] + Dg[1][cl][s2] + Dg[2][cl][s2] + Dg[3][cl][s2];
        g_D[(size_t)(c0 + cl) * S_DIM + s0 + s2] = v;
    }
}

// ---------------------------------------------------------------------------
// Banded 1-D convolution out[s,t] = sum_tau D[tau+2,s] * G(t-tau).
// ---------------------------------------------------------------------------
__global__ __launch_bounds__(256)
void conv_kernel(const float* __restrict__ sig, float* __restrict__ out)
{
    __shared__ float Db[2 * RMAX + 33][64];
    __shared__ float Gs[2 * RMAX + 1];

    const int s0 = blockIdx.x * 64;
    const int t0 = blockIdx.y * 32;
    const int tid = threadIdx.x;

    const float sigma  = sig[0];
    const float inv2s2 = 1.0f / (2.0f * sigma * sigma);
    const float coef   = 0.3989422804f / sqrtf(sigma * sigma);
    int R = (int)ceilf(sigma * 7.746f);
    if (R < 1) R = 1;
    if (R > RMAX) R = RMAX;
    const int nG = 2 * R + 1;
    const int rows = 2 * R + 33;
    const int rlo = t0 - R + 2;

    for (int i = tid; i < nG; i += 256) {
        float d = (float)(i - R);
        Gs[i] = coef * expf(-d * d * inv2s2);
    }
    for (int idx = tid; idx < rows * 64; idx += 256) {
        int ri = idx >> 6, s2 = idx & 63;
        int c = rlo + ri;
        Db[ri][s2] = (c >= 0 && c < T_DIM + 4) ?
            g_D[(size_t)c * S_DIM + s0 + s2] : 0.f;
    }
    __syncthreads();

    const int sl = tid & 31;
    const int tq = tid >> 5;
    const int tb = tq * 4;

    float acc0[4] = {0.f, 0.f, 0.f, 0.f};
    float acc1[4] = {0.f, 0.f, 0.f, 0.f};

    for (int ri = 0; ri < rows; ri++) {
        float v0 = Db[ri][sl];
        float v1 = Db[ri][sl + 32];
#pragma unroll
        for (int k = 0; k < 4; k++) {
            int gi = ri - tb - k;
            if (gi >= 0 && gi < nG) {
                float w = Gs[gi];
                acc0[k] = fmaf(v0, w, acc0[k]);
                acc1[k] = fmaf(v1, w, acc1[k]);
            }
        }
    }

    *(float4*)&out[(size_t)(s0 + sl) * T_DIM + t0 + tb] =
        make_float4(acc0[0], acc0[1], acc0[2], acc0[3]);
    *(float4*)&out[(size_t)(s0 + sl + 32) * T_DIM + t0 + tb] =
        make_float4(acc1[0], acc1[1], acc1[2], acc1[3]);
}

// ---------------------------------------------------------------------------
extern "C" void kernel_launch(void* const* d_in, const int* in_sizes, int n_in,
                              void* d_out, int out_size)
{
    const float* x    = (const float*)d_in[0];
    const float* zpos = (const float*)d_in[1];
    const float* mask = (const float*)d_in[2];
    const float* Wp1  = (const float*)d_in[3];
    const float* bp1  = (const float*)d_in[4];
    const float* Wp2  = (const float*)d_in[5];
    const float* bp2  = (const float*)d_in[6];
    const float* Wa1  = (const float*)d_in[7];
    const float* ba1  = (const float*)d_in[8];
    const float* Wa2  = (const float*)d_in[9];
    const float* ba2  = (const float*)d_in[10];
    const float* sig  = (const float*)d_in[11];

    int ne = in_sizes[1];
    if (ne > NE_MAX) ne = NE_MAX;

    const int dyn_bytes = 6 * BTILE;   // 2 A tiles + 4 B tiles = 208896 B
    cudaFuncSetAttribute(mlp_mma_kernel,
                         cudaFuncAttributeMaxDynamicSharedMemorySize, dyn_bytes);

    prep_kernel<<<dim3(NSTILE, 4), 256>>>(Wp2, Wa2);
    bucket_kernel<<<NBUCKET, 256>>>(zpos, ne);

    mlp_mma_kernel<<<dim3(NSTILE, EGRP), 256, dyn_bytes>>>(
        x, mask, Wp1, bp1, bp2, Wa1, ba1, ba2, ne);

    stageA_kernel<<<dim3(S_DIM / 32, NBUCKET), 128>>>();

    conv_kernel<<<dim3(S_DIM / 64, T_DIM / 32), 256>>>(sig, (float*)d_out);
}

// round 7
// speedup vs baseline: 5.1610x; 1.2304x over previous
#include <cuda_runtime.h>
#include <cuda_bf16.h>
#include <math.h>
#include <stdint.h>

#define S_DIM 1024
#define T_DIM 1024
#define HID_DIM 128
#define NE_MAX 32000
#define NBUCKET 33
#define BWID 32             // bucket width in tap columns
#define BCAP 2048
#define RMAX 72
#define NSTILE 8
#define EGRP 18
#define BTILE 34816u        // one [128][136] bf16 tile in bytes
#define LDT 136             // padded row length (bf16 elems)

// ---------------- scratch (__device__ globals) ----------------
__device__ __align__(16) __nv_bfloat16 g_respb[(size_t)NE_MAX * S_DIM];     // [e][s]
__device__ __align__(16) float g_D[(size_t)NBUCKET * BWID * S_DIM];         // [c][s]
__device__ int   g_bcnt[NBUCKET];
__device__ int   g_bidx[NBUCKET * BCAP];
__device__ float g_bz[NBUCKET * BCAP];
// bf16 weight tiles [stile][p_hi,p_lo,a_hi,a_lo][128k][136n]
__device__ __align__(16) unsigned char g_Bprep[(size_t)NSTILE * 4 * BTILE];

// ---------------- helpers ----------------
__device__ __forceinline__ uint32_t smem_u32(const void* p) {
    uint32_t a;
    asm("{ .reg .u64 t; cvta.to.shared.u64 t, %1; cvt.u32.u64 %0, t; }"
        : "=r"(a) : "l"(p));
    return a;
}
__device__ __forceinline__ void ldsm_x4(uint32_t* r, uint32_t addr) {
    asm volatile("ldmatrix.sync.aligned.m8n8.x4.shared.b16 {%0,%1,%2,%3}, [%4];"
                 : "=r"(r[0]), "=r"(r[1]), "=r"(r[2]), "=r"(r[3]) : "r"(addr));
}
__device__ __forceinline__ void ldsm_x4_t(uint32_t* r, uint32_t addr) {
    asm volatile("ldmatrix.sync.aligned.m8n8.x4.trans.shared.b16 {%0,%1,%2,%3}, [%4];"
                 : "=r"(r[0]), "=r"(r[1]), "=r"(r[2]), "=r"(r[3]) : "r"(addr));
}
__device__ __forceinline__ void mma_bf16(float* c, const uint32_t* a, const uint32_t* b) {
    asm volatile("mma.sync.aligned.m16n8k16.row.col.f32.bf16.bf16.f32 "
                 "{%0,%1,%2,%3}, {%4,%5,%6,%7}, {%8,%9}, {%0,%1,%2,%3};"
                 : "+f"(c[0]), "+f"(c[1]), "+f"(c[2]), "+f"(c[3])
                 : "r"(a[0]), "r"(a[1]), "r"(a[2]), "r"(a[3]), "r"(b[0]), "r"(b[1]));
}

// ---------------------------------------------------------------------------
// Prep: split W2 into bf16 hi/lo tiles [k][136] row-major.
// which: 0=p_hi 1=p_lo 2=a_hi 3=a_lo
// ---------------------------------------------------------------------------
__global__ void prep_kernel(const float* __restrict__ Wp2, const float* __restrict__ Wa2)
{
    const int stile = blockIdx.x, which = blockIdx.y;
    const int s0 = stile * 128;
    const float* W2 = (which >= 2) ? Wa2 : Wp2;
    const int split = which & 1;
    __nv_bfloat16* dst = (__nv_bfloat16*)(g_Bprep + ((size_t)stile * 4 + which) * BTILE);
    for (int idx = threadIdx.x; idx < 128 * 128; idx += 256) {
        int k = idx >> 7, n = idx & 127;
        float w = W2[(size_t)k * S_DIM + s0 + n];
        __nv_bfloat16 hi = __float2bfloat16(w);
        __nv_bfloat16 v = split ? __float2bfloat16(w - __bfloat162float(hi)) : hi;
        dst[k * LDT + n] = v;
    }
}

// ---------------------------------------------------------------------------
// Bucket electrons (deterministic, index order), 4 per thread per round.
// Bucket b holds electrons with k=floor(z) in [32b-5, 32b+31].
// ---------------------------------------------------------------------------
__global__ void bucket_kernel(const float* __restrict__ zpos, int ne)
{
    const int b = blockIdx.x;
    const int tid = threadIdx.x;
    const float lob = (float)(b * BWID - 5);
    const float hib = (float)(b * BWID + BWID);

    __shared__ int wsum[4][8];
    __shared__ int base0;
    if (tid == 0) base0 = 0;
    __syncthreads();

    const int lane = tid & 31, w = tid >> 5;
    for (int cb = 0; cb < ne; cb += 1024) {
        float z[4]; bool kp[4]; unsigned bm[4];
#pragma unroll
        for (int q = 0; q < 4; q++) {
            int e = cb + q * 256 + tid;
            kp[q] = false; z[q] = 0.f;
            if (e < ne) { z[q] = zpos[e]; kp[q] = (z[q] >= lob) && (z[q] < hib); }
        }
#pragma unroll
        for (int q = 0; q < 4; q++) bm[q] = __ballot_sync(0xffffffffu, kp[q]);
        if (lane == 0)
#pragma unroll
            for (int q = 0; q < 4; q++) wsum[q][w] = __popc(bm[q]);
        __syncthreads();
        if (tid == 0) {
            int run = base0;
#pragma unroll
            for (int q = 0; q < 4; q++)
#pragma unroll
                for (int ww = 0; ww < 8; ww++) {
                    int t = wsum[q][ww]; wsum[q][ww] = run; run += t;
                }
            base0 = run;
        }
        __syncthreads();
#pragma unroll
        for (int q = 0; q < 4; q++) {
            if (kp[q]) {
                int p = wsum[q][w] + __popc(bm[q] & ((1u << lane) - 1u));
                if (p < BCAP) {
                    g_bidx[b * BCAP + p] = cb + q * 256 + tid;
                    g_bz[b * BCAP + p] = z[q];
                }
            }
        }
        __syncthreads();
    }
    if (tid == 0) g_bcnt[b] = (base0 < BCAP) ? base0 : BCAP;
}

// ---------------------------------------------------------------------------
// MLP via mma.sync bf16. Grid (NSTILE=8, EGRP=18), 256 threads / 8 warps.
// CTA: 128-sensor tile, B (4 weight tiles) resident; loops 128-electron tiles.
// Warp tile 32e x 64s (warps: 4 over e, 2 over s). Output: bf16 g_respb.
// ---------------------------------------------------------------------------
__global__ __launch_bounds__(256, 1)
void mlp_mma_kernel(const float* __restrict__ x, const float* __restrict__ maskv,
                    const float* __restrict__ Wp1, const float* __restrict__ bp1,
                    const float* __restrict__ bp2,
                    const float* __restrict__ Wa1, const float* __restrict__ ba1,
                    const float* __restrict__ ba2,
                    int ne)
{
    extern __shared__ __align__(16) unsigned char dyn[];
    __shared__ __align__(16) float xs[128][4];
    __shared__ __align__(16) float W1s[2][3][HID_DIM];
    __shared__ __align__(16) float b1s[2][HID_DIM];
    __shared__ __align__(16) float bb[2][128];

    const int tid = threadIdx.x;
    const int wid = tid >> 5, lane = tid & 31;
    const int wy = wid >> 1;          // 0..3 over electrons
    const int wx = wid & 1;           // 0..1 over sensors
    const int stile = blockIdx.x, gy = blockIdx.y;
    const int s0 = stile * 128;
    const int ntiles = (ne + 127) / 128;

    unsigned char* Ap = dyn;
    unsigned char* Aa = dyn + BTILE;
    unsigned char* Bt = dyn + 2 * BTILE;

    for (int i = tid; i < 3 * HID_DIM; i += 256) {
        (&W1s[0][0][0])[i] = Wp1[i];
        (&W1s[1][0][0])[i] = Wa1[i];
    }
    for (int i = tid; i < HID_DIM; i += 256) {
        b1s[0][i] = bp1[i];
        b1s[1][i] = ba1[i];
        bb[0][i] = bp2[s0 + i];
        bb[1][i] = ba2[s0 + i];
    }
    {
        const uint4* src = (const uint4*)(g_Bprep + (size_t)stile * 4 * BTILE);
        uint4* d4 = (uint4*)Bt;
        for (int i = tid; i < (int)(4 * BTILE / 16); i += 256) d4[i] = src[i];
    }
    __syncthreads();

    const uint32_t ApS = smem_u32(Ap), AaS = smem_u32(Aa), BtS = smem_u32(Bt);
    const uint32_t lmOff = (uint32_t)(lane & 15) * (LDT * 2) + (uint32_t)(lane >> 4) * 16;

    for (int et = gy; et < ntiles; et += EGRP) {
        const int e0 = et * 128;

        if (tid < 128) {
            int e = e0 + tid;
            if (e < ne) {
                xs[tid][0] = x[e * 3 + 0];
                xs[tid][1] = x[e * 3 + 1];
                xs[tid][2] = x[e * 3 + 2];
            } else {
                xs[tid][0] = 0.f; xs[tid][1] = 0.f; xs[tid][2] = 0.f;
            }
        }
        __syncthreads();

        // H (fp32) -> bf16 pairs into A tiles [el][k], row stride LDT
        for (int i = tid; i < 16384; i += 256) {
            int m = i >> 13, el = (i >> 6) & 127, k = (i & 63) * 2;
            float x0 = xs[el][0], x1 = xs[el][1], x2 = xs[el][2];
            float h0 = b1s[m][k]     + x0 * W1s[m][0][k]     + x1 * W1s[m][1][k]     + x2 * W1s[m][2][k];
            float h1 = b1s[m][k + 1] + x0 * W1s[m][0][k + 1] + x1 * W1s[m][1][k + 1] + x2 * W1s[m][2][k + 1];
            h0 = fmaxf(h0, 0.f); h1 = fmaxf(h1, 0.f);
            __nv_bfloat162 v = __floats2bfloat162_rn(h0, h1);
            unsigned char* base = m ? Aa : Ap;
            *(uint32_t*)(base + el * (LDT * 2) + k * 2) = *(uint32_t*)&v;
        }
        __syncthreads();

        float accP[2][8][4], accA[2][8][4];
#pragma unroll
        for (int mt = 0; mt < 2; mt++)
#pragma unroll
            for (int nt = 0; nt < 8; nt++)
#pragma unroll
                for (int j = 0; j < 4; j++) { accP[mt][nt][j] = 0.f; accA[mt][nt][j] = 0.f; }

#pragma unroll
        for (int sp = 0; sp < 2; sp++) {
            const uint32_t BpS = BtS + (uint32_t)sp * BTILE;
            const uint32_t BaS = BtS + (uint32_t)(2 + sp) * BTILE;
#pragma unroll
            for (int ks = 0; ks < 8; ks++) {
                const uint32_t kb = (uint32_t)ks * 32;
                const uint32_t krow = (uint32_t)ks * 16 * (LDT * 2);
                uint32_t a0[4], a1[4], bf[4][4];
                // ---- prob MLP ----
                ldsm_x4(a0, ApS + (uint32_t)(wy * 32) * (LDT * 2) + kb + lmOff);
                ldsm_x4(a1, ApS + (uint32_t)(wy * 32 + 16) * (LDT * 2) + kb + lmOff);
#pragma unroll
                for (int nb = 0; nb < 4; nb++)
                    ldsm_x4_t(bf[nb], BpS + krow + (uint32_t)(wx * 64 + nb * 16) * 2 + lmOff);
#pragma unroll
                for (int nb = 0; nb < 4; nb++) {
                    mma_bf16(accP[0][2 * nb],     a0, &bf[nb][0]);
                    mma_bf16(accP[0][2 * nb + 1], a0, &bf[nb][2]);
                    mma_bf16(accP[1][2 * nb],     a1, &bf[nb][0]);
                    mma_bf16(accP[1][2 * nb + 1], a1, &bf[nb][2]);
                }
                // ---- amp MLP ----
                ldsm_x4(a0, AaS + (uint32_t)(wy * 32) * (LDT * 2) + kb + lmOff);
                ldsm_x4(a1, AaS + (uint32_t)(wy * 32 + 16) * (LDT * 2) + kb + lmOff);
#pragma unroll
                for (int nb = 0; nb < 4; nb++)
                    ldsm_x4_t(bf[nb], BaS + krow + (uint32_t)(wx * 64 + nb * 16) * 2 + lmOff);
#pragma unroll
                for (int nb = 0; nb < 4; nb++) {
                    mma_bf16(accA[0][2 * nb],     a0, &bf[nb][0]);
                    mma_bf16(accA[0][2 * nb + 1], a0, &bf[nb][2]);
                    mma_bf16(accA[1][2 * nb],     a1, &bf[nb][0]);
                    mma_bf16(accA[1][2 * nb + 1], a1, &bf[nb][2]);
                }
            }
        }

        // epilogue: fused bias+sigmoid+amp+mask, bf16 stores
        const int rbase = wy * 32 + (lane >> 2);
        const int colb = wx * 64 + (lane & 3) * 2;
#pragma unroll
        for (int mt = 0; mt < 2; mt++) {
            int ra = e0 + rbase + mt * 16;
            int rb = ra + 8;
            float mka = (ra < ne) ? maskv[ra] : 0.f;
            float mkb = (rb < ne) ? maskv[rb] : 0.f;
#pragma unroll
            for (int nt = 0; nt < 8; nt++) {
                int col = colb + nt * 8;
                float bp0 = bb[0][col], bp1v = bb[0][col + 1];
                float ba0 = bb[1][col], ba1v = bb[1][col + 1];
                float p0 = accP[mt][nt][0] + bp0, p1 = accP[mt][nt][1] + bp1v;
                float p2 = accP[mt][nt][2] + bp0, p3 = accP[mt][nt][3] + bp1v;
                float A0 = accA[mt][nt][0] + ba0, A1 = accA[mt][nt][1] + ba1v;
                float A2 = accA[mt][nt][2] + ba0, A3 = accA[mt][nt][3] + ba1v;
                float o0 = A0 * mka * (1.0f / (1.0f + expf(-p0)));
                float o1 = A1 * mka * (1.0f / (1.0f + expf(-p1)));
                float o2 = A2 * mkb * (1.0f / (1.0f + expf(-p2)));
                float o3 = A3 * mkb * (1.0f / (1.0f + expf(-p3)));
                if (ra < ne) *(__nv_bfloat162*)&g_respb[(size_t)ra * S_DIM + s0 + col] =
                    __floats2bfloat162_rn(o0, o1);
                if (rb < ne) *(__nv_bfloat162*)&g_respb[(size_t)rb * S_DIM + s0 + col] =
                    __floats2bfloat162_rn(o2, o3);
            }
        }
    }
}

// ---------------------------------------------------------------------------
// Stage A: tap scatter. grid (32 s-tiles, 33 buckets), 256 threads / 8 warps,
// each warp a private 32x32 smem slab (deterministic order), bf16 resp reads.
// ---------------------------------------------------------------------------
__global__ __launch_bounds__(256)
void stageA_kernel()
{
    const int s0 = blockIdx.x * 32;
    const int b = blockIdx.y;
    const int tid = threadIdx.x;
    const int warp = tid >> 5, sl = tid & 31;

    __shared__ float Dg[8][BWID][32];     // 32 KB
    __shared__ float wch[256][6];         // 6 KB
    __shared__ int   ech[256];
    __shared__ int   kch[256];

    for (int i = tid; i < 8 * BWID * 32; i += 256) (&Dg[0][0][0])[i] = 0.f;
    __syncthreads();

    const int cnt = g_bcnt[b];
    const int c0 = b * BWID;

    for (int base = 0; base < cnt; base += 256) {
        int n = cnt - base; if (n > 256) n = 256;
        if (tid < n) {
            float z = g_bz[b * BCAP + base + tid];
            float kf = floorf(z);
            float f = z - kf;
            float t0 = f + 2.f, t1 = f + 1.f, t2 = f, t3 = f - 1.f,
                  t4 = f - 2.f, t5 = f - 3.f;
            wch[tid][0] = t1 * t2 * t3 * t4 * t5 * (-1.f / 120.f);
            wch[tid][1] = t0 * t2 * t3 * t4 * t5 * ( 1.f /  24.f);
            wch[tid][2] = t0 * t1 * t3 * t4 * t5 * (-1.f /  12.f);
            wch[tid][3] = t0 * t1 * t2 * t4 * t5 * ( 1.f /  12.f);
            wch[tid][4] = t0 * t1 * t2 * t3 * t5 * (-1.f /  24.f);
            wch[tid][5] = t0 * t1 * t2 * t3 * t4 * ( 1.f / 120.f);
            kch[tid] = (int)kf;
            ech[tid] = g_bidx[b * BCAP + base + tid];
        }
        __syncthreads();

        for (int i0 = warp * 4; i0 < n; i0 += 32) {
            float r[4];
#pragma unroll
            for (int q = 0; q < 4; q++) {
                int i = i0 + q;
                r[q] = (i < n) ?
                    __bfloat162float(g_respb[(size_t)ech[i] * S_DIM + s0 + sl]) : 0.f;
            }
#pragma unroll
            for (int q = 0; q < 4; q++) {
                int i = i0 + q;
                if (i < n) {
                    int cl0 = kch[i] - c0;
#pragma unroll
                    for (int j = 0; j < 6; j++) {
                        int cl = cl0 + j;
                        if (cl >= 0 && cl < BWID)
                            Dg[warp][cl][sl] += r[q] * wch[i][j];
                    }
                }
            }
        }
        __syncthreads();
    }

    for (int idx = tid; idx < BWID * 32; idx += 256) {
        int cl = idx >> 5, s2 = idx & 31;
        float v = 0.f;
#pragma unroll
        for (int w = 0; w < 8; w++) v += Dg[w][cl][s2];
        g_D[(size_t)(c0 + cl) * S_DIM + s0 + s2] = v;
    }
}

// ---------------------------------------------------------------------------
// Banded 1-D convolution out[s,t] = sum_tau D[tau+2,s] * G(t-tau).
// ---------------------------------------------------------------------------
__global__ __launch_bounds__(256)
void conv_kernel(const float* __restrict__ sig, float* __restrict__ out)
{
    __shared__ float Db[2 * RMAX + 33][64];
    __shared__ float Gs[2 * RMAX + 1];

    const int s0 = blockIdx.x * 64;
    const int t0 = blockIdx.y * 32;
    const int tid = threadIdx.x;

    const float sigma  = sig[0];
    const float inv2s2 = 1.0f / (2.0f * sigma * sigma);
    const float coef   = 0.3989422804f / sqrtf(sigma * sigma);
    int R = (int)ceilf(sigma * 7.746f);
    if (R < 1) R = 1;
    if (R > RMAX) R = RMAX;
    const int nG = 2 * R + 1;
    const int rows = 2 * R + 33;
    const int rlo = t0 - R + 2;

    for (int i = tid; i < nG; i += 256) {
        float d = (float)(i - R);
        Gs[i] = coef * expf(-d * d * inv2s2);
    }
    for (int idx = tid; idx < rows * 64; idx += 256) {
        int ri = idx >> 6, s2 = idx & 63;
        int c = rlo + ri;
        Db[ri][s2] = (c >= 0 && c < T_DIM + 4) ?
            g_D[(size_t)c * S_DIM + s0 + s2] : 0.f;
    }
    __syncthreads();

    const int sl = tid & 31;
    const int tq = tid >> 5;
    const int tb = tq * 4;

    float acc0[4] = {0.f, 0.f, 0.f, 0.f};
    float acc1[4] = {0.f, 0.f, 0.f, 0.f};

    for (int ri = 0; ri < rows; ri++) {
        float v0 = Db[ri][sl];
        float v1 = Db[ri][sl + 32];
#pragma unroll
        for (int k = 0; k < 4; k++) {
            int gi = ri - tb - k;
            if (gi >= 0 && gi < nG) {
                float w = Gs[gi];
                acc0[k] = fmaf(v0, w, acc0[k]);
                acc1[k] = fmaf(v1, w, acc1[k]);
            }
        }
    }

    *(float4*)&out[(size_t)(s0 + sl) * T_DIM + t0 + tb] =
        make_float4(acc0[0], acc0[1], acc0[2], acc0[3]);
    *(float4*)&out[(size_t)(s0 + sl + 32) * T_DIM + t0 + tb] =
        make_float4(acc1[0], acc1[1], acc1[2], acc1[3]);
}

// ---------------------------------------------------------------------------
extern "C" void kernel_launch(void* const* d_in, const int* in_sizes, int n_in,
                              void* d_out, int out_size)
{
    const float* x    = (const float*)d_in[0];
    const float* zpos = (const float*)d_in[1];
    const float* mask = (const float*)d_in[2];
    const float* Wp1  = (const float*)d_in[3];
    const float* bp1  = (const float*)d_in[4];
    const float* Wp2  = (const float*)d_in[5];
    const float* bp2  = (const float*)d_in[6];
    const float* Wa1  = (const float*)d_in[7];
    const float* ba1  = (const float*)d_in[8];
    const float* Wa2  = (const float*)d_in[9];
    const float* ba2  = (const float*)d_in[10];
    const float* sig  = (const float*)d_in[11];

    int ne = in_sizes[1];
    if (ne > NE_MAX) ne = NE_MAX;

    const int dyn_bytes = 6 * BTILE;   // 2 A tiles + 4 B tiles = 208896 B
    cudaFuncSetAttribute(mlp_mma_kernel,
                         cudaFuncAttributeMaxDynamicSharedMemorySize, dyn_bytes);

    prep_kernel<<<dim3(NSTILE, 4), 256>>>(Wp2, Wa2);
    bucket_kernel<<<NBUCKET, 256>>>(zpos, ne);

    mlp_mma_kernel<<<dim3(NSTILE, EGRP), 256, dyn_bytes>>>(
        x, mask, Wp1, bp1, bp2, Wa1, ba1, ba2, ne);

    stageA_kernel<<<dim3(S_DIM / 32, NBUCKET), 256>>>();

    conv_kernel<<<dim3(S_DIM / 64, T_DIM / 32), 256>>>(sig, (float*)d_out);
}